// round 14
// baseline (speedup 1.0000x reference)
#include <cuda_runtime.h>
#include <cuda_bf16.h>
#include <mma.h>
#include <math.h>

using namespace nvcuda;

// Problem constants
#define BB 64
#define WW 16
#define CC 64
#define TT 1024
#define DE 64
#define NBW 1024           // B*W
#define NROWS 65536        // B*W*C
#define XR_ELEMS 67108864  // B*C*W*T

// -------- device scratch (no allocations allowed) --------
__device__ float g_stat[NROWS];                 // [bw][c]
__device__ float g_Z[CC * DE];                  // [c][d]
__device__ __nv_bfloat16 g_Abf[2 * CC * CC];    // rows 0-63 hi(A2), 64-127 lo
__device__ __nv_bfloat16 g_xh[XR_ELEMS];        // bf16 hi plane of x
__device__ __nv_bfloat16 g_xl[XR_ELEMS];        // bf16 lo plane of x

__device__ __forceinline__ unsigned smem_u32(const void* p) {
    unsigned a;
    asm("{ .reg .u64 t; cvta.to.shared.u64 t, %1; cvt.u32.u64 %0, t; }"
        : "=r"(a) : "l"(p));
    return a;
}
__device__ __forceinline__ void cp_async16(unsigned dst, const void* src) {
    asm volatile("cp.async.cg.shared.global [%0], [%1], 16;" :: "r"(dst), "l"(src));
}
#define CP_COMMIT() asm volatile("cp.async.commit_group;")
#define CP_WAIT0()  asm volatile("cp.async.wait_group 0;")

// ================= Kernel 1: per-row stats + bf16 hi/lo conversion =================
__global__ void k_stats_conv(const float* __restrict__ x) {
    int warp = (blockIdx.x * blockDim.x + threadIdx.x) >> 5;
    int lane = threadIdx.x & 31;
    if (warp >= NROWS) return;
    const float4* p = reinterpret_cast<const float4*>(x) + (size_t)warp * 256;
    unsigned long long* ph = reinterpret_cast<unsigned long long*>(g_xh) + (size_t)warp * 256;
    unsigned long long* pl = reinterpret_cast<unsigned long long*>(g_xl) + (size_t)warp * 256;
    float s1 = 0.f, s2 = 0.f;
#pragma unroll
    for (int k = 0; k < 8; k++) {
        int idx = lane + 32 * k;
        float4 v = p[idx];
        s1 += (v.x + v.y) + (v.z + v.w);
        s2 += v.x * v.x + v.y * v.y + v.z * v.z + v.w * v.w;
        __nv_bfloat16 h0 = __float2bfloat16(v.x), h1 = __float2bfloat16(v.y);
        __nv_bfloat16 h2 = __float2bfloat16(v.z), h3 = __float2bfloat16(v.w);
        __nv_bfloat16 l0 = __float2bfloat16(v.x - __bfloat162float(h0));
        __nv_bfloat16 l1 = __float2bfloat16(v.y - __bfloat162float(h1));
        __nv_bfloat16 l2 = __float2bfloat16(v.z - __bfloat162float(h2));
        __nv_bfloat16 l3 = __float2bfloat16(v.w - __bfloat162float(h3));
        __nv_bfloat162 hp0 = __halves2bfloat162(h0, h1), hp1 = __halves2bfloat162(h2, h3);
        __nv_bfloat162 lp0 = __halves2bfloat162(l0, l1), lp1 = __halves2bfloat162(l2, l3);
        unsigned long long hw =
            (unsigned long long)*reinterpret_cast<unsigned*>(&hp0) |
            ((unsigned long long)*reinterpret_cast<unsigned*>(&hp1) << 32);
        unsigned long long lw =
            (unsigned long long)*reinterpret_cast<unsigned*>(&lp0) |
            ((unsigned long long)*reinterpret_cast<unsigned*>(&lp1) << 32);
        ph[idx] = hw;
        pl[idx] = lw;
    }
#pragma unroll
    for (int off = 16; off > 0; off >>= 1) {
        s1 += __shfl_xor_sync(0xffffffffu, s1, off);
        s2 += __shfl_xor_sync(0xffffffffu, s2, off);
    }
    if (lane == 0) g_stat[warp] = 0.5f * (s1 + s2) * (1.0f / 1024.0f);
}

// ================= Kernel 2: Z_mean[c][d] =================
__global__ void k_zmean(const float* __restrict__ Wp) {
    __shared__ float scol[NBW];
    __shared__ float swp[DE];
    __shared__ float part[256];
    int c = blockIdx.x;
    int tid = threadIdx.x;
    if (tid < DE) swp[tid] = Wp[tid];
    for (int i = tid; i < NBW; i += 256) scol[i] = g_stat[i * CC + c];
    __syncthreads();
    int d = tid & 63, grp = tid >> 6;
    float w = swp[d];
    float s = 0.f;
    for (int bw = grp; bw < NBW; bw += 4) s += tanhf(scol[bw] * w);
    part[tid] = s;
    __syncthreads();
    if (tid < 64) {
        float z = (part[tid] + part[tid + 64] + part[tid + 128] + part[tid + 192]) *
                  (1.0f / 1024.0f);
        g_Z[c * DE + tid] = z;
    }
}

// ================= Kernel 3: graph build (single block, 1024 thr) =================
__device__ __forceinline__ unsigned rotl32(unsigned v, int s) {
    return (v << s) | (v >> (32 - s));
}
__device__ __forceinline__ void threefry_0_42(unsigned c0, unsigned c1,
                                              unsigned& o0, unsigned& o1) {
    const unsigned ks0 = 0u, ks1 = 42u, ks2 = 0u ^ 42u ^ 0x1BD11BDAu;
    unsigned x0 = c0 + ks0, x1 = c1 + ks1;
#define TF_RND(r) { x0 += x1; x1 = rotl32(x1, r); x1 ^= x0; }
    TF_RND(13) TF_RND(15) TF_RND(26) TF_RND(6)  x0 += ks1; x1 += ks2 + 1u;
    TF_RND(17) TF_RND(29) TF_RND(16) TF_RND(24) x0 += ks2; x1 += ks0 + 2u;
    TF_RND(13) TF_RND(15) TF_RND(26) TF_RND(6)  x0 += ks0; x1 += ks1 + 3u;
    TF_RND(17) TF_RND(29) TF_RND(16) TF_RND(24) x0 += ks1; x1 += ks2 + 4u;
    TF_RND(13) TF_RND(15) TF_RND(26) TF_RND(6)  x0 += ks2; x1 += ks0 + 5u;
#undef TF_RND
    o0 = x0; o1 = x1;
}
// Partitionable threefry: counter (0, idx); sample = XOR-fold of output words.
__device__ __forceinline__ float gumbel_at(int idx) {
    unsigned o0, o1;
    threefry_0_42(0u, (unsigned)idx, o0, o1);
    unsigned bits = o0 ^ o1;
    float u = __uint_as_float((bits >> 9) | 0x3f800000u) - 1.0f;
    const float tiny = 1.17549435e-38f;
    float r = fmaxf(tiny, u + tiny);
    return -logf(-logf(r));
}
__device__ __forceinline__ float gelu_exact(float v) {
    return 0.5f * v * (1.0f + erff(v * 0.70710678118654752f));
}
__device__ __forceinline__ float softplus_f(float v) {
    return fmaxf(v, 0.f) + log1pf(expf(-fabsf(v)));
}

#define GNT 1024
#define EPT 4

__global__ void __launch_bounds__(GNT) k_graph(
        const float* __restrict__ w1, const float* __restrict__ b1,
        const float* __restrict__ w2, const float* __restrict__ b2,
        const float* __restrict__ pbeta, const float* __restrict__ pgamma,
        const float* __restrict__ ptemp, float* __restrict__ outA) {
    __shared__ float sA[4096];
    __shared__ float sS[4096];
    __shared__ float ssq[64];
    __shared__ float sdinv[64];
    __shared__ unsigned long long smask[64];
    __shared__ float sw1[16], sb1[16], sw2[16];
    int tid = threadIdx.x;
    if (tid < 16) { sw1[tid] = w1[tid]; sb1[tid] = b1[tid]; sw2[tid] = w2[tid]; }
    float beta = *pbeta, gamma = *pgamma, b2v = *b2;
    float invt = 1.0f / fmaxf(*ptemp, 1e-6f);

#pragma unroll
    for (int k = 0; k < EPT; k++) sS[tid + GNT * k] = g_Z[tid + GNT * k];
    __syncthreads();
    if (tid < 64) {
        float s = 0.f;
#pragma unroll
        for (int m = 0; m < 64; m++) { float z = sS[tid * 64 + m]; s += z * z; }
        ssq[tid] = s;
    }
    __syncthreads();

    float d2r[EPT];
#pragma unroll
    for (int k = 0; k < EPT; k++) {
        int e = tid + GNT * k, i = e >> 6, j = e & 63;
        float dot = 0.f;
        for (int m = 0; m < 64; m++) dot += sS[i * 64 + m] * sS[j * 64 + m];
        float v = ssq[i] + ssq[j] - 2.0f * dot;
        d2r[k] = fmaxf(v, 0.f) * 0.5f;
        sA[e] = (i == j) ? 1.f : 0.f;
    }
    __syncthreads();

    for (int step = 0; step < 2; step++) {
#pragma unroll
        for (int k = 0; k < EPT; k++) {
            int e = tid + GNT * k;
            float a = sA[e] - 0.2f * d2r[k];
            float s = b2v;
#pragma unroll
            for (int m = 0; m < 16; m++) {
                float h = gelu_exact(fmaf(a, sw1[m], sb1[m]));
                s = fmaf(h, sw2[m], s);
            }
            a = a + beta * (softplus_f(s) * gamma);
            sA[e] = a;
        }
        __syncthreads();
        float r1[EPT], r2[EPT];
#pragma unroll
        for (int k = 0; k < EPT; k++) {
            int e = tid + GNT * k, i = e >> 6, j = e & 63;
            r1[k] = sA[e]; r2[k] = sA[j * 64 + i];
        }
        __syncthreads();
#pragma unroll
        for (int k = 0; k < EPT; k++) {
            int e = tid + GNT * k, i = e >> 6, j = e & 63;
            float v = 0.5f * (r1[k] + r2[k]);
            sA[e] = fmaxf(v, 0.f) + ((i == j) ? 1.f : 0.f);
        }
        __syncthreads();
    }

#pragma unroll
    for (int k = 0; k < EPT; k++) {
        int e = tid + GNT * k;
        sS[e] = (sA[e] + gumbel_at(e)) * invt;
    }
    __syncthreads();

    {   // warp-parallel top-16, 32 warps x 2 rows
        int warp = tid >> 5, lane = tid & 31;
        const float NEG_INF = __int_as_float(0xff800000);
#pragma unroll
        for (int rr = 0; rr < 2; rr++) {
            int r = warp * 2 + rr;
            float v0 = sS[r * 64 + lane];
            float v1 = sS[r * 64 + 32 + lane];
            bool p0 = false, p1 = false;
            for (int p = 0; p < 16; p++) {
                float bv; int bi;
                if (v0 >= v1) { bv = v0; bi = lane; }
                else          { bv = v1; bi = lane + 32; }
#pragma unroll
                for (int off = 16; off > 0; off >>= 1) {
                    float ov = __shfl_xor_sync(0xffffffffu, bv, off);
                    int   oi = __shfl_xor_sync(0xffffffffu, bi, off);
                    if (ov > bv || (ov == bv && oi < bi)) { bv = ov; bi = oi; }
                }
                if (bi == lane)           { p0 = true; v0 = NEG_INF; }
                else if (bi == lane + 32) { p1 = true; v1 = NEG_INF; }
            }
            unsigned lo = __ballot_sync(0xffffffffu, p0);
            unsigned hi = __ballot_sync(0xffffffffu, p1);
            if (lane == 0)
                smask[r] = (unsigned long long)lo | ((unsigned long long)hi << 32);
        }
    }
    __syncthreads();
#pragma unroll
    for (int k = 0; k < EPT; k++) {
        int e = tid + GNT * k, i = e >> 6, j = e & 63;
        if (!((smask[i] >> j) & 1ull)) sA[e] = 0.f;
    }
    __syncthreads();
    {
        float r1[EPT], r2[EPT];
#pragma unroll
        for (int k = 0; k < EPT; k++) {
            int e = tid + GNT * k, i = e >> 6, j = e & 63;
            r1[k] = sA[e]; r2[k] = sA[j * 64 + i];
        }
        __syncthreads();
#pragma unroll
        for (int k = 0; k < EPT; k++) {
            int e = tid + GNT * k, i = e >> 6, j = e & 63;
            float v = fmaxf(0.5f * (r1[k] + r2[k]), 0.f) + ((i == j) ? 1.f : 0.f);
            sA[e] = v;
        }
        __syncthreads();
    }
    if (tid < 64) {
        float s = 0.f;
        for (int j = 0; j < 64; j++) s += sA[tid * 64 + j];
        sdinv[tid] = rsqrtf(fmaxf(s, 1e-6f));
    }
    __syncthreads();
#pragma unroll
    for (int k = 0; k < EPT; k++) {
        int e = tid + GNT * k, i = e >> 6, j = e & 63;
        float v = sdinv[i] * sA[e] * sdinv[j] + ((i == j) ? 1.f : 0.f);
        sA[e] = v;
        outA[e] = v;
    }
    __syncthreads();
    // A2 = A @ A, emitted directly as bf16 hi/lo stack for the GEMM
#pragma unroll
    for (int k = 0; k < EPT; k++) {
        int e = tid + GNT * k, i = e >> 6, j = e & 63;
        float s = 0.f;
        for (int m = 0; m < 64; m++) s += sA[i * 64 + m] * sA[m * 64 + j];
        __nv_bfloat16 ah = __float2bfloat16(s);
        g_Abf[e] = ah;
        g_Abf[e + 4096] = __float2bfloat16(s - __bfloat162float(ah));
    }
}

// ================= Kernel 4: out = A2 @ x, pure bf16 WMMA GEMM =================
// Padded smem strides (conflict-free ldmatrix):
//   A stride 72 elems (144 B), x planes stride 264 elems (528 B)
#define A_LD   72
#define X_LD   264
#define SMP_A  0
#define SMP_XH (128 * A_LD * 2)                    // 18432
#define SMP_XL (SMP_XH + 64 * X_LD * 2)            // 52224
#define SMP_TOT (SMP_XL + 64 * X_LD * 2)           // 86016

__global__ void __launch_bounds__(256) k_gemm(float* __restrict__ out) {
    extern __shared__ char smem[];
    __nv_bfloat16* sA = reinterpret_cast<__nv_bfloat16*>(smem + SMP_A);
    __nv_bfloat16* sXH = reinterpret_cast<__nv_bfloat16*>(smem + SMP_XH);
    __nv_bfloat16* sXL = reinterpret_cast<__nv_bfloat16*>(smem + SMP_XL);
    int tid = threadIdx.x, warp = tid >> 5;
    int bw = blockIdx.x >> 2, tgrp = (blockIdx.x & 3) << 8;
    unsigned sbase = smem_u32(smem);

    // cp.async A stack: 128 rows x 128 B (8 chunks), padded stride 144 B
#pragma unroll
    for (int k = 0; k < 4; k++) {
        int idx = tid + 256 * k;          // 0..1023
        int row = idx >> 3, ch = idx & 7;
        cp_async16(sbase + SMP_A + row * 144 + ch * 16,
                   reinterpret_cast<const char*>(g_Abf) + row * 128 + ch * 16);
    }
    // cp.async x planes: 64 rows x 512 B (32 chunks) each, padded stride 528 B
    const char* xh = reinterpret_cast<const char*>(g_xh) +
                     (((size_t)bw << 16) + tgrp) * 2;
    const char* xl = reinterpret_cast<const char*>(g_xl) +
                     (((size_t)bw << 16) + tgrp) * 2;
#pragma unroll
    for (int k = 0; k < 8; k++) {
        int idx = tid + 256 * k;          // 0..2047
        int j = idx >> 5, ch = idx & 31;
        cp_async16(sbase + SMP_XH + j * 528 + ch * 16, xh + (size_t)j * 2048 + ch * 16);
        cp_async16(sbase + SMP_XL + j * 528 + ch * 16, xl + (size_t)j * 2048 + ch * 16);
    }
    CP_COMMIT();
    CP_WAIT0();
    __syncthreads();

    size_t obase = (size_t)(bw >> 4) * 1048576 + (size_t)(bw & 15) * 1024 + tgrp;

    // Each warp: 2 N-tiles of 16 t
#pragma unroll
    for (int nt2 = 0; nt2 < 2; nt2++) {
        int n0 = (warp * 2 + nt2) * 16;
        wmma::fragment<wmma::accumulator, 16, 16, 16, float> acc[8];
#pragma unroll
        for (int mt = 0; mt < 8; mt++) wmma::fill_fragment(acc[mt], 0.0f);

#pragma unroll
        for (int k = 0; k < 4; k++) {
            wmma::fragment<wmma::matrix_a, 16, 16, 16, __nv_bfloat16, wmma::row_major> af[8];
#pragma unroll
            for (int mt = 0; mt < 8; mt++)
                wmma::load_matrix_sync(af[mt], sA + (mt * 16) * A_LD + k * 16, A_LD);

            wmma::fragment<wmma::matrix_b, 16, 16, 16, __nv_bfloat16, wmma::row_major> bh, bl;
            wmma::load_matrix_sync(bh, sXH + (k * 16) * X_LD + n0, X_LD);
            wmma::load_matrix_sync(bl, sXL + (k * 16) * X_LD + n0, X_LD);
#pragma unroll
            for (int mt = 0; mt < 8; mt++) wmma::mma_sync(acc[mt], af[mt], bh, acc[mt]);
#pragma unroll
            for (int mt = 0; mt < 8; mt++) wmma::mma_sync(acc[mt], af[mt], bl, acc[mt]);
        }

        // out rows c = D_hi[c] + D_lo[c] (fragment-wise), store to gmem
#pragma unroll
        for (int mt = 0; mt < 4; mt++) {
#pragma unroll
            for (int e = 0; e < acc[mt].num_elements; e++)
                acc[mt].x[e] += acc[mt + 4].x[e];
            wmma::store_matrix_sync(out + obase + (size_t)(mt * 16) * 16384 + n0,
                                    acc[mt], 16384, wmma::mem_row_major);
        }
    }
}

// ================= launch =================
extern "C" void kernel_launch(void* const* d_in, const int* in_sizes, int n_in,
                              void* d_out, int out_size) {
    const float* x     = (const float*)d_in[0];
    const float* Wp    = (const float*)d_in[1];
    const float* w1    = (const float*)d_in[2];
    const float* b1    = (const float*)d_in[3];
    const float* w2    = (const float*)d_in[4];
    const float* b2    = (const float*)d_in[5];
    const float* beta  = (const float*)d_in[6];
    const float* gamma = (const float*)d_in[7];
    const float* temp  = (const float*)d_in[8];
    float* out = (float*)d_out;

    static int inited = 0;
    if (!inited) {
        cudaFuncSetAttribute(k_gemm, cudaFuncAttributeMaxDynamicSharedMemorySize, SMP_TOT);
        inited = 1;
    }

    k_stats_conv<<<8192, 256>>>(x);
    k_zmean<<<64, 256>>>(Wp);
    k_graph<<<1, GNT>>>(w1, b1, w2, b2, beta, gamma, temp, out + XR_ELEMS);
    k_gemm<<<4096, 256, SMP_TOT>>>(out);
}

// round 15
// speedup vs baseline: 1.1723x; 1.1723x over previous
#include <cuda_runtime.h>
#include <cuda_bf16.h>
#include <mma.h>
#include <math.h>

using namespace nvcuda;

// Problem constants
#define BB 64
#define WW 16
#define CC 64
#define TT 1024
#define DE 64
#define NBW 1024           // B*W
#define NROWS 65536        // B*W*C
#define XR_ELEMS 67108864  // B*C*W*T

// -------- device scratch (no allocations allowed) --------
__device__ float g_stat[NROWS];                 // [bw][c]
__device__ float g_Zp[8 * CC * DE];             // per-slab partial Z sums
__device__ __nv_bfloat16 g_Abf[2 * CC * CC];    // rows 0-63 hi(A2), 64-127 lo
__device__ __nv_bfloat16 g_xh[XR_ELEMS];        // bf16 hi plane of x
__device__ __nv_bfloat16 g_xl[XR_ELEMS];        // bf16 lo plane of x

__device__ __forceinline__ unsigned smem_u32(const void* p) {
    unsigned a;
    asm("{ .reg .u64 t; cvta.to.shared.u64 t, %1; cvt.u32.u64 %0, t; }"
        : "=r"(a) : "l"(p));
    return a;
}
__device__ __forceinline__ void cp_async16(unsigned dst, const void* src) {
    asm volatile("cp.async.cg.shared.global [%0], [%1], 16;" :: "r"(dst), "l"(src));
}
#define CP_COMMIT() asm volatile("cp.async.commit_group;")
#define CP_WAIT0()  asm volatile("cp.async.wait_group 0;")

// ================= Kernel 1: per-row stats + bf16 hi/lo conversion =================
__global__ void k_stats_conv(const float* __restrict__ x) {
    int warp = (blockIdx.x * blockDim.x + threadIdx.x) >> 5;
    int lane = threadIdx.x & 31;
    if (warp >= NROWS) return;
    const float4* p = reinterpret_cast<const float4*>(x) + (size_t)warp * 256;
    unsigned long long* ph = reinterpret_cast<unsigned long long*>(g_xh) + (size_t)warp * 256;
    unsigned long long* pl = reinterpret_cast<unsigned long long*>(g_xl) + (size_t)warp * 256;
    float s1 = 0.f, s2 = 0.f;
#pragma unroll
    for (int k = 0; k < 8; k++) {
        int idx = lane + 32 * k;
        float4 v = p[idx];
        s1 += (v.x + v.y) + (v.z + v.w);
        s2 += v.x * v.x + v.y * v.y + v.z * v.z + v.w * v.w;
        __nv_bfloat16 h0 = __float2bfloat16(v.x), h1 = __float2bfloat16(v.y);
        __nv_bfloat16 h2 = __float2bfloat16(v.z), h3 = __float2bfloat16(v.w);
        __nv_bfloat16 l0 = __float2bfloat16(v.x - __bfloat162float(h0));
        __nv_bfloat16 l1 = __float2bfloat16(v.y - __bfloat162float(h1));
        __nv_bfloat16 l2 = __float2bfloat16(v.z - __bfloat162float(h2));
        __nv_bfloat16 l3 = __float2bfloat16(v.w - __bfloat162float(h3));
        __nv_bfloat162 hp0 = __halves2bfloat162(h0, h1), hp1 = __halves2bfloat162(h2, h3);
        __nv_bfloat162 lp0 = __halves2bfloat162(l0, l1), lp1 = __halves2bfloat162(l2, l3);
        unsigned long long hw =
            (unsigned long long)*reinterpret_cast<unsigned*>(&hp0) |
            ((unsigned long long)*reinterpret_cast<unsigned*>(&hp1) << 32);
        unsigned long long lw =
            (unsigned long long)*reinterpret_cast<unsigned*>(&lp0) |
            ((unsigned long long)*reinterpret_cast<unsigned*>(&lp1) << 32);
        ph[idx] = hw;
        pl[idx] = lw;
    }
#pragma unroll
    for (int off = 16; off > 0; off >>= 1) {
        s1 += __shfl_xor_sync(0xffffffffu, s1, off);
        s2 += __shfl_xor_sync(0xffffffffu, s2, off);
    }
    if (lane == 0) g_stat[warp] = 0.5f * (s1 + s2) * (1.0f / 1024.0f);
}

// ================= Kernel 2: Z partial sums, 8 bw-slabs x 64 channels =================
__global__ void k_zmean_part(const float* __restrict__ Wp) {
    __shared__ float scol[128];
    __shared__ float swp[DE];
    __shared__ float part[256];
    int c = blockIdx.x, slab = blockIdx.y;
    int tid = threadIdx.x;
    if (tid < DE) swp[tid] = Wp[tid];
    if (tid < 128) scol[tid] = g_stat[(slab * 128 + tid) * CC + c];
    __syncthreads();
    int d = tid & 63, grp = tid >> 6;
    float w = swp[d];
    float s = 0.f;
#pragma unroll
    for (int bw = grp; bw < 128; bw += 4) s += tanhf(scol[bw] * w);
    part[tid] = s;
    __syncthreads();
    if (tid < 64)
        g_Zp[slab * 4096 + c * 64 + tid] =
            part[tid] + part[tid + 64] + part[tid + 128] + part[tid + 192];
}

// ================= Kernel 3: graph build (single block, 1024 thr) =================
__device__ __forceinline__ unsigned rotl32(unsigned v, int s) {
    return (v << s) | (v >> (32 - s));
}
__device__ __forceinline__ void threefry_0_42(unsigned c0, unsigned c1,
                                              unsigned& o0, unsigned& o1) {
    const unsigned ks0 = 0u, ks1 = 42u, ks2 = 0u ^ 42u ^ 0x1BD11BDAu;
    unsigned x0 = c0 + ks0, x1 = c1 + ks1;
#define TF_RND(r) { x0 += x1; x1 = rotl32(x1, r); x1 ^= x0; }
    TF_RND(13) TF_RND(15) TF_RND(26) TF_RND(6)  x0 += ks1; x1 += ks2 + 1u;
    TF_RND(17) TF_RND(29) TF_RND(16) TF_RND(24) x0 += ks2; x1 += ks0 + 2u;
    TF_RND(13) TF_RND(15) TF_RND(26) TF_RND(6)  x0 += ks0; x1 += ks1 + 3u;
    TF_RND(17) TF_RND(29) TF_RND(16) TF_RND(24) x0 += ks1; x1 += ks2 + 4u;
    TF_RND(13) TF_RND(15) TF_RND(26) TF_RND(6)  x0 += ks2; x1 += ks0 + 5u;
#undef TF_RND
    o0 = x0; o1 = x1;
}
// Partitionable threefry: counter (0, idx); sample = XOR-fold of output words.
__device__ __forceinline__ float gumbel_at(int idx) {
    unsigned o0, o1;
    threefry_0_42(0u, (unsigned)idx, o0, o1);
    unsigned bits = o0 ^ o1;
    float u = __uint_as_float((bits >> 9) | 0x3f800000u) - 1.0f;
    const float tiny = 1.17549435e-38f;
    float r = fmaxf(tiny, u + tiny);
    return -logf(-logf(r));
}
__device__ __forceinline__ float gelu_exact(float v) {
    return 0.5f * v * (1.0f + erff(v * 0.70710678118654752f));
}
__device__ __forceinline__ float softplus_f(float v) {
    return fmaxf(v, 0.f) + log1pf(expf(-fabsf(v)));
}

#define GNT 1024
#define EPT 4

__global__ void __launch_bounds__(GNT) k_graph(
        const float* __restrict__ w1, const float* __restrict__ b1,
        const float* __restrict__ w2, const float* __restrict__ b2,
        const float* __restrict__ pbeta, const float* __restrict__ pgamma,
        const float* __restrict__ ptemp, float* __restrict__ outA) {
    __shared__ float sA[4096];
    __shared__ float sS[4096];
    __shared__ float ssq[64];
    __shared__ float sdinv[64];
    __shared__ unsigned long long smask[64];
    __shared__ float sw1[16], sb1[16], sw2[16];
    int tid = threadIdx.x;
    if (tid < 16) { sw1[tid] = w1[tid]; sb1[tid] = b1[tid]; sw2[tid] = w2[tid]; }
    float beta = *pbeta, gamma = *pgamma, b2v = *b2;
    float invt = 1.0f / fmaxf(*ptemp, 1e-6f);

    // reduce Z partial sums (8 slabs) -> Z mean
#pragma unroll
    for (int k = 0; k < EPT; k++) {
        int e = tid + GNT * k;
        float s = 0.f;
#pragma unroll
        for (int sl = 0; sl < 8; sl++) s += g_Zp[sl * 4096 + e];
        sS[e] = s * (1.0f / 1024.0f);
    }
    __syncthreads();
    if (tid < 64) {
        float s = 0.f;
#pragma unroll
        for (int m = 0; m < 64; m++) { float z = sS[tid * 64 + m]; s += z * z; }
        ssq[tid] = s;
    }
    __syncthreads();

    float d2r[EPT];
#pragma unroll
    for (int k = 0; k < EPT; k++) {
        int e = tid + GNT * k, i = e >> 6, j = e & 63;
        float dot = 0.f;
        for (int m = 0; m < 64; m++) dot += sS[i * 64 + m] * sS[j * 64 + m];
        float v = ssq[i] + ssq[j] - 2.0f * dot;
        d2r[k] = fmaxf(v, 0.f) * 0.5f;
        sA[e] = (i == j) ? 1.f : 0.f;
    }
    __syncthreads();

    for (int step = 0; step < 2; step++) {
#pragma unroll
        for (int k = 0; k < EPT; k++) {
            int e = tid + GNT * k;
            float a = sA[e] - 0.2f * d2r[k];
            float s = b2v;
#pragma unroll
            for (int m = 0; m < 16; m++) {
                float h = gelu_exact(fmaf(a, sw1[m], sb1[m]));
                s = fmaf(h, sw2[m], s);
            }
            a = a + beta * (softplus_f(s) * gamma);
            sA[e] = a;
        }
        __syncthreads();
        float r1[EPT], r2[EPT];
#pragma unroll
        for (int k = 0; k < EPT; k++) {
            int e = tid + GNT * k, i = e >> 6, j = e & 63;
            r1[k] = sA[e]; r2[k] = sA[j * 64 + i];
        }
        __syncthreads();
#pragma unroll
        for (int k = 0; k < EPT; k++) {
            int e = tid + GNT * k, i = e >> 6, j = e & 63;
            float v = 0.5f * (r1[k] + r2[k]);
            sA[e] = fmaxf(v, 0.f) + ((i == j) ? 1.f : 0.f);
        }
        __syncthreads();
    }

#pragma unroll
    for (int k = 0; k < EPT; k++) {
        int e = tid + GNT * k;
        sS[e] = (sA[e] + gumbel_at(e)) * invt;
    }
    __syncthreads();

    {   // warp-parallel top-16, 32 warps x 2 rows
        int warp = tid >> 5, lane = tid & 31;
        const float NEG_INF = __int_as_float(0xff800000);
#pragma unroll
        for (int rr = 0; rr < 2; rr++) {
            int r = warp * 2 + rr;
            float v0 = sS[r * 64 + lane];
            float v1 = sS[r * 64 + 32 + lane];
            bool p0 = false, p1 = false;
            for (int p = 0; p < 16; p++) {
                float bv; int bi;
                if (v0 >= v1) { bv = v0; bi = lane; }
                else          { bv = v1; bi = lane + 32; }
#pragma unroll
                for (int off = 16; off > 0; off >>= 1) {
                    float ov = __shfl_xor_sync(0xffffffffu, bv, off);
                    int   oi = __shfl_xor_sync(0xffffffffu, bi, off);
                    if (ov > bv || (ov == bv && oi < bi)) { bv = ov; bi = oi; }
                }
                if (bi == lane)           { p0 = true; v0 = NEG_INF; }
                else if (bi == lane + 32) { p1 = true; v1 = NEG_INF; }
            }
            unsigned lo = __ballot_sync(0xffffffffu, p0);
            unsigned hi = __ballot_sync(0xffffffffu, p1);
            if (lane == 0)
                smask[r] = (unsigned long long)lo | ((unsigned long long)hi << 32);
        }
    }
    __syncthreads();
#pragma unroll
    for (int k = 0; k < EPT; k++) {
        int e = tid + GNT * k, i = e >> 6, j = e & 63;
        if (!((smask[i] >> j) & 1ull)) sA[e] = 0.f;
    }
    __syncthreads();
    {
        float r1[EPT], r2[EPT];
#pragma unroll
        for (int k = 0; k < EPT; k++) {
            int e = tid + GNT * k, i = e >> 6, j = e & 63;
            r1[k] = sA[e]; r2[k] = sA[j * 64 + i];
        }
        __syncthreads();
#pragma unroll
        for (int k = 0; k < EPT; k++) {
            int e = tid + GNT * k, i = e >> 6, j = e & 63;
            float v = fmaxf(0.5f * (r1[k] + r2[k]), 0.f) + ((i == j) ? 1.f : 0.f);
            sA[e] = v;
        }
        __syncthreads();
    }
    if (tid < 64) {
        float s = 0.f;
        for (int j = 0; j < 64; j++) s += sA[tid * 64 + j];
        sdinv[tid] = rsqrtf(fmaxf(s, 1e-6f));
    }
    __syncthreads();
#pragma unroll
    for (int k = 0; k < EPT; k++) {
        int e = tid + GNT * k, i = e >> 6, j = e & 63;
        float v = sdinv[i] * sA[e] * sdinv[j] + ((i == j) ? 1.f : 0.f);
        sA[e] = v;
        outA[e] = v;
    }
    __syncthreads();
    // A2 = A @ A, emitted directly as bf16 hi/lo stack for the GEMM
#pragma unroll
    for (int k = 0; k < EPT; k++) {
        int e = tid + GNT * k, i = e >> 6, j = e & 63;
        float s = 0.f;
        for (int m = 0; m < 64; m++) s += sA[i * 64 + m] * sA[m * 64 + j];
        __nv_bfloat16 ah = __float2bfloat16(s);
        g_Abf[e] = ah;
        g_Abf[e + 4096] = __float2bfloat16(s - __bfloat162float(ah));
    }
}

// ================= Kernel 4: out = A2 @ x, pure bf16 WMMA GEMM =================
// Padded smem strides (conflict-free ldmatrix):
//   A stride 72 elems (144 B), x planes stride 264 elems (528 B)
#define A_LD   72
#define X_LD   264
#define SMP_A  0
#define SMP_XH (128 * A_LD * 2)                    // 18432
#define SMP_XL (SMP_XH + 64 * X_LD * 2)            // 52224
#define SMP_TOT (SMP_XL + 64 * X_LD * 2)           // 86016

__global__ void __launch_bounds__(256, 2) k_gemm(float* __restrict__ out) {
    extern __shared__ char smem[];
    __nv_bfloat16* sA = reinterpret_cast<__nv_bfloat16*>(smem + SMP_A);
    __nv_bfloat16* sXH = reinterpret_cast<__nv_bfloat16*>(smem + SMP_XH);
    __nv_bfloat16* sXL = reinterpret_cast<__nv_bfloat16*>(smem + SMP_XL);
    int tid = threadIdx.x, warp = tid >> 5;
    int bw = blockIdx.x >> 2, tgrp = (blockIdx.x & 3) << 8;
    unsigned sbase = smem_u32(smem);

    // cp.async A stack: 128 rows x 128 B (8 chunks), padded stride 144 B
#pragma unroll
    for (int k = 0; k < 4; k++) {
        int idx = tid + 256 * k;          // 0..1023
        int row = idx >> 3, ch = idx & 7;
        cp_async16(sbase + SMP_A + row * 144 + ch * 16,
                   reinterpret_cast<const char*>(g_Abf) + row * 128 + ch * 16);
    }
    // cp.async x planes: 64 rows x 512 B (32 chunks) each, padded stride 528 B
    const char* xh = reinterpret_cast<const char*>(g_xh) +
                     (((size_t)bw << 16) + tgrp) * 2;
    const char* xl = reinterpret_cast<const char*>(g_xl) +
                     (((size_t)bw << 16) + tgrp) * 2;
#pragma unroll
    for (int k = 0; k < 8; k++) {
        int idx = tid + 256 * k;          // 0..2047
        int j = idx >> 5, ch = idx & 31;
        cp_async16(sbase + SMP_XH + j * 528 + ch * 16, xh + (size_t)j * 2048 + ch * 16);
        cp_async16(sbase + SMP_XL + j * 528 + ch * 16, xl + (size_t)j * 2048 + ch * 16);
    }
    CP_COMMIT();
    CP_WAIT0();
    __syncthreads();

    size_t obase = (size_t)(bw >> 4) * 1048576 + (size_t)(bw & 15) * 1024 + tgrp;

    // Each warp: 2 N-tiles of 16 t
#pragma unroll
    for (int nt2 = 0; nt2 < 2; nt2++) {
        int n0 = (warp * 2 + nt2) * 16;
        wmma::fragment<wmma::accumulator, 16, 16, 16, float> acc[8];
#pragma unroll
        for (int mt = 0; mt < 8; mt++) wmma::fill_fragment(acc[mt], 0.0f);

#pragma unroll
        for (int k = 0; k < 4; k++) {
            wmma::fragment<wmma::matrix_a, 16, 16, 16, __nv_bfloat16, wmma::row_major> af[8];
#pragma unroll
            for (int mt = 0; mt < 8; mt++)
                wmma::load_matrix_sync(af[mt], sA + (mt * 16) * A_LD + k * 16, A_LD);

            wmma::fragment<wmma::matrix_b, 16, 16, 16, __nv_bfloat16, wmma::row_major> bh, bl;
            wmma::load_matrix_sync(bh, sXH + (k * 16) * X_LD + n0, X_LD);
            wmma::load_matrix_sync(bl, sXL + (k * 16) * X_LD + n0, X_LD);
#pragma unroll
            for (int mt = 0; mt < 8; mt++) wmma::mma_sync(acc[mt], af[mt], bh, acc[mt]);
#pragma unroll
            for (int mt = 0; mt < 8; mt++) wmma::mma_sync(acc[mt], af[mt], bl, acc[mt]);
        }

        // out rows c = D_hi[c] + D_lo[c] (fragment-wise), store to gmem
#pragma unroll
        for (int mt = 0; mt < 4; mt++) {
#pragma unroll
            for (int e = 0; e < acc[mt].num_elements; e++)
                acc[mt].x[e] += acc[mt + 4].x[e];
            wmma::store_matrix_sync(out + obase + (size_t)(mt * 16) * 16384 + n0,
                                    acc[mt], 16384, wmma::mem_row_major);
        }
    }
}

// ================= launch =================
extern "C" void kernel_launch(void* const* d_in, const int* in_sizes, int n_in,
                              void* d_out, int out_size) {
    const float* x     = (const float*)d_in[0];
    const float* Wp    = (const float*)d_in[1];
    const float* w1    = (const float*)d_in[2];
    const float* b1    = (const float*)d_in[3];
    const float* w2    = (const float*)d_in[4];
    const float* b2    = (const float*)d_in[5];
    const float* beta  = (const float*)d_in[6];
    const float* gamma = (const float*)d_in[7];
    const float* temp  = (const float*)d_in[8];
    float* out = (float*)d_out;

    static int inited = 0;
    if (!inited) {
        cudaFuncSetAttribute(k_gemm, cudaFuncAttributeMaxDynamicSharedMemorySize, SMP_TOT);
        inited = 1;
    }

    k_stats_conv<<<8192, 256>>>(x);
    k_zmean_part<<<dim3(64, 8), 256>>>(Wp);
    k_graph<<<1, GNT>>>(w1, b1, w2, b2, beta, gamma, temp, out + XR_ELEMS);
    k_gemm<<<4096, 256, SMP_TOT>>>(out);
}